// round 3
// baseline (speedup 1.0000x reference)
#include <cuda_runtime.h>
#include <math.h>

// x (2,16,256,256) f32, conv_w (32,16,4,4), conv_b (32) -> out (2,32,256,256) f32.
// Ring of 40 offsets (radius 5), stable-select 16 smallest sigmoid-sims,
// rank-indexed 32x(16*16) mat-vec per pixel.
// out[o] = bias[o] + sum_c wsum[c][o]*xc[c] - sum_{r,c} w[r][c][o]*xr[r][c]
// (smem holds -w so the inner loop is pure fma on xr).

#define B_      2
#define CCH     16
#define HH      256
#define WWIDTH  256
#define HW      (HH*WWIDTH)
#define OUTC    32
#define NOFF    40
#define NSEL    16

#define TW 32
#define TH 8
#define NTHR (TW*TH)           // 256
#define SW 42                  // TW + 2*5
#define SH 18                  // TH + 2*5
#define CPLANE (SW*SH)         // 756
#define XS_FLOATS (CPLANE*CCH)        // 12096
#define WS_FLOATS (NSEL*CCH*OUTC)     // 8192
#define WSUM_FLOATS (CCH*OUTC)        // 512
#define CB_FLOATS 32
#define SEL_WORDS (NSEL*NTHR)         // 4096
#define SMEM_BYTES ((XS_FLOATS + WS_FLOATS + WSUM_FLOATS + CB_FLOATS + SEL_WORDS)*4)

// Ring offsets, order matching _prf_offsets:
//  j 0..10 : dx=-5,   dy=j-5
//  j 11..19: dx=j-15, dy=+5
//  j 20..30: dx=+5,   dy=j-25
//  j 31..39: dx=j-35, dy=-5
__host__ __device__ constexpr int dxOf(int j){ return j<11 ? -5 : (j<20 ? j-15 : (j<31 ? 5 : j-35)); }
__host__ __device__ constexpr int dyOf(int j){ return j<11 ? j-5 : (j<20 ? 5 : (j<31 ? j-25 : -5)); }
__host__ __device__ constexpr int offOf(int j){ return dxOf(j)*SW + dyOf(j); }

typedef unsigned long long u64;

__device__ __forceinline__ u64 pack2(float a, float b){
    u64 r;
    asm("mov.b64 %0, {%1,%2};" : "=l"(r) : "f"(a), "f"(b));
    return r;
}
__device__ __forceinline__ void fma2(u64 &acc, u64 a, u64 b){
    asm("fma.rn.f32x2 %0, %1, %2, %0;" : "+l"(acc) : "l"(a), "l"(b));
}
__device__ __forceinline__ float2 unpack2(u64 v){
    float2 f;
    asm("mov.b64 {%0,%1}, %2;" : "=f"(f.x), "=f"(f.y) : "l"(v));
    return f;
}

__global__ __launch_bounds__(NTHR, 2)
void pkc2d_kernel(const float* __restrict__ x,
                  const float* __restrict__ cw,
                  const float* __restrict__ cb,
                  float* __restrict__ out)
{
    extern __shared__ float sm[];
    float*    xs   = sm;                        // [c][sy][sx] 16 x 18 x 42
    float*    ws   = sm + XS_FLOATS;            // [r][c][o]   16 x 16 x 32  (NEGATED)
    float*    wsum = ws + WS_FLOATS;            // [c][o]      16 x 32  (sum_r w, positive)
    float*    cbs  = wsum + WSUM_FLOATS;        // [32]
    unsigned* selp = (unsigned*)(cbs + CB_FLOATS); // [r][tid] 16 x 256

    const int tx = threadIdx.x, ty = threadIdx.y;
    const int tid = ty*TW + tx;
    const int gx0 = blockIdx.x*TW, gy0 = blockIdx.y*TH;
    const int bz  = blockIdx.z;

    const float* xb = x + (size_t)bz * CCH * HW;

    // ---- cooperative loads ----
    for (int i = tid; i < XS_FLOATS; i += NTHR) {
        int c   = i / CPLANE;
        int rem = i - c*CPLANE;
        int sy  = rem / SW;
        int sx  = rem - sy*SW;
        int gy  = gy0 + sy - 5;
        int gxp = gx0 + sx - 5;
        float v = 0.f;
        if ((unsigned)gy < (unsigned)HH && (unsigned)gxp < (unsigned)WWIDTH)
            v = xb[c*HW + gy*WWIDTH + gxp];
        xs[i] = v;
    }
    // ws[((r*16)+c)*32 + o] = -cw[o*256 + c*16 + r]
    for (int i = tid; i < WS_FLOATS; i += NTHR) {
        int o  = i & 31;
        int rc = i >> 5;
        int r  = rc >> 4;
        int c  = rc & 15;
        ws[i] = -cw[o*256 + c*16 + r];
    }
    // wsum[c*32+o] = sum_r cw[o*256+c*16+r]  (16 contiguous floats)
    for (int i = tid; i < WSUM_FLOATS; i += NTHR) {
        int o = i & 31;
        int c = i >> 5;
        const float4* p = reinterpret_cast<const float4*>(cw + o*256 + c*16);
        float4 a = p[0], b = p[1], cc = p[2], d = p[3];
        wsum[i] = ((a.x+a.y)+(a.z+a.w)) + ((b.x+b.y)+(b.z+b.w))
                + ((cc.x+cc.y)+(cc.z+cc.w)) + ((d.x+d.y)+(d.z+d.w));
    }
    if (tid < 32) cbs[tid] = cb[tid];
    __syncthreads();

    // ================= Phase 1: per-own-pixel selection =================
    {
        const int base = (ty+5)*SW + (tx+5);

        float xc[CCH];
        #pragma unroll
        for (int c = 0; c < CCH; ++c) xc[c] = xs[c*CPLANE + base];

        // sims (sequential channel-order add to track the reference reduction)
        float sims[NOFF];
        #pragma unroll
        for (int j = 0; j < NOFF; ++j) {
            const int off = offOf(j);
            float s = 0.f;
            #pragma unroll
            for (int c = 0; c < CCH; ++c)
                s = __fadd_rn(s, __fmul_rn(xs[c*CPLANE + base + off], xc[c]));
            s *= 0.0625f;
            sims[j] = 1.0f / (1.0f + expf(-s));
        }

        // rank[j] = #{jp: sims[jp]<sims[j]} + #{jp<j: sims[jp]==sims[j]}
        #pragma unroll
        for (int j = 0; j < NOFF; ++j) {
            int rk = 0;
            #pragma unroll
            for (int jp = 0; jp < NOFF; ++jp) {
                if (jp < j)       rk += (sims[jp] <= sims[j]) ? 1 : 0;
                else if (jp > j)  rk += (sims[jp] <  sims[j]) ? 1 : 0;
            }
            if (rk < NSEL)
                selp[rk*NTHR + tid] = (unsigned)(offOf(j) + 512);
        }
    }
    __syncthreads();

    // ================= Phase 2: pixel-pair / half-OUTC mat-vec =================
    // thread t: ph = t>>7 -> o in [16*ph, 16*ph+16); pixels p0 = t&127 (rows 0..3)
    // and p1 = p0+128 (rows 4..7) of the 32x8 tile.
    const int pp = tid & 127;
    const int ph = tid >> 7;
    const int px = pp & 31;
    const int py = pp >> 5;

    const int b0 = (py+5)*SW + (px+5);
    const int b1 = b0 + 4*SW;

    // ---- pre-pass: acc = bias + sum_c wsum[c][o]*xc[c] ----
    u64 accA[8], accB[8];
    #pragma unroll
    for (int q = 0; q < 8; ++q) {
        u64 seed = pack2(cbs[ph*16 + 2*q], cbs[ph*16 + 2*q + 1]);
        accA[q] = seed;
        accB[q] = seed;
    }
    {
        const ulonglong2* wsp = reinterpret_cast<const ulonglong2*>(wsum + (ph << 4));
        #pragma unroll
        for (int c = 0; c < CCH; ++c) {
            const float xc0 = xs[c*CPLANE + b0];
            const float xc1 = xs[c*CPLANE + b1];
            const u64 p0 = pack2(xc0, xc0);
            const u64 p1 = pack2(xc1, xc1);
            ulonglong2 wa = wsp[c*8 + 0];
            ulonglong2 wb = wsp[c*8 + 1];
            ulonglong2 wc = wsp[c*8 + 2];
            ulonglong2 wd = wsp[c*8 + 3];
            fma2(accA[0], wa.x, p0); fma2(accB[0], wa.x, p1);
            fma2(accA[1], wa.y, p0); fma2(accB[1], wa.y, p1);
            fma2(accA[2], wb.x, p0); fma2(accB[2], wb.x, p1);
            fma2(accA[3], wb.y, p0); fma2(accB[3], wb.y, p1);
            fma2(accA[4], wc.x, p0); fma2(accB[4], wc.x, p1);
            fma2(accA[5], wc.y, p0); fma2(accB[5], wc.y, p1);
            fma2(accA[6], wd.x, p0); fma2(accB[6], wd.x, p1);
            fma2(accA[7], wd.y, p0); fma2(accB[7], wd.y, p1);
        }
    }

    // ---- main loop: acc += (-w)[r][c][o] * xr ----
    #pragma unroll 1
    for (int r = 0; r < NSEL; ++r) {
        const int a0 = b0 + (int)selp[r*NTHR + pp]       - 512;
        const int a1 = b1 + (int)selp[r*NTHR + pp + 128] - 512;
        const ulonglong2* wp =
            reinterpret_cast<const ulonglong2*>(ws + (r << 9) + (ph << 4));
        #pragma unroll
        for (int c = 0; c < CCH; ++c) {
            const float xr0 = xs[c*CPLANE + a0];
            const float xr1 = xs[c*CPLANE + a1];
            const u64 p0 = pack2(xr0, xr0);
            const u64 p1 = pack2(xr1, xr1);
            ulonglong2 wa = wp[c*8 + 0];
            ulonglong2 wb = wp[c*8 + 1];
            ulonglong2 wc = wp[c*8 + 2];
            ulonglong2 wd = wp[c*8 + 3];
            fma2(accA[0], wa.x, p0); fma2(accB[0], wa.x, p1);
            fma2(accA[1], wa.y, p0); fma2(accB[1], wa.y, p1);
            fma2(accA[2], wb.x, p0); fma2(accB[2], wb.x, p1);
            fma2(accA[3], wb.y, p0); fma2(accB[3], wb.y, p1);
            fma2(accA[4], wc.x, p0); fma2(accB[4], wc.x, p1);
            fma2(accA[5], wc.y, p0); fma2(accB[5], wc.y, p1);
            fma2(accA[6], wd.x, p0); fma2(accB[6], wd.x, p1);
            fma2(accA[7], wd.y, p0); fma2(accB[7], wd.y, p1);
        }
    }

    // ---- store: 16 o-channels x 2 pixels ----
    const int gx = gx0 + px;
    const int gy_a = gy0 + py;
    const int gy_b = gy_a + 4;
    float* ob = out + (size_t)bz*OUTC*HW + (size_t)(ph*16)*HW + gx;
    #pragma unroll
    for (int q = 0; q < 8; ++q) {
        float2 va = unpack2(accA[q]);
        float2 vb = unpack2(accB[q]);
        ob[(2*q  )*HW + gy_a*WWIDTH] = va.x;
        ob[(2*q+1)*HW + gy_a*WWIDTH] = va.y;
        ob[(2*q  )*HW + gy_b*WWIDTH] = vb.x;
        ob[(2*q+1)*HW + gy_b*WWIDTH] = vb.y;
    }
}

extern "C" void kernel_launch(void* const* d_in, const int* in_sizes, int n_in,
                              void* d_out, int out_size)
{
    const float* x  = (const float*)d_in[0];
    const float* cw = (const float*)d_in[1];
    const float* cb = (const float*)d_in[2];
    float* out = (float*)d_out;

    cudaFuncSetAttribute(pkc2d_kernel,
                         cudaFuncAttributeMaxDynamicSharedMemorySize, SMEM_BYTES);

    dim3 block(TW, TH, 1);
    dim3 grid(WWIDTH/TW, HH/TH, B_);
    pkc2d_kernel<<<grid, block, SMEM_BYTES>>>(x, cw, cb, out);
}

// round 4
// speedup vs baseline: 1.0987x; 1.0987x over previous
#include <cuda_runtime.h>
#include <math.h>

// x (2,16,256,256) f32, conv_w (32,16,4,4), conv_b (32) -> out (2,32,256,256) f32.
// Ring of 40 offsets (radius 5), stable-select 16 smallest sigmoid-sims,
// rank-indexed 32x(16*16) mat-vec per pixel.

#define B_      2
#define CCH     16
#define HH      256
#define WWIDTH  256
#define HW      (HH*WWIDTH)
#define OUTC    32
#define NOFF    40
#define NSEL    16

#define TW 32
#define TH 8
#define NTHR (TW*TH)           // 256
#define SW 42                  // TW + 2*5
#define SH 18                  // TH + 2*5
#define CPLANE (SW*SH)         // 756
#define XS_FLOATS (CPLANE*CCH)        // 12096
#define WS_FLOATS (NSEL*CCH*OUTC)     // 8192
#define CB_FLOATS 32
#define SEL_WORDS (NSEL*NTHR)         // 4096
#define SMEM_BYTES ((XS_FLOATS + WS_FLOATS + CB_FLOATS + SEL_WORDS)*4)

// Ring offsets, order matching _prf_offsets:
//  j 0..10 : dx=-5,   dy=j-5
//  j 11..19: dx=j-15, dy=+5
//  j 20..30: dx=+5,   dy=j-25
//  j 31..39: dx=j-35, dy=-5
__host__ __device__ constexpr int dxOf(int j){ return j<11 ? -5 : (j<20 ? j-15 : (j<31 ? 5 : j-35)); }
__host__ __device__ constexpr int dyOf(int j){ return j<11 ? j-5 : (j<20 ? 5 : (j<31 ? j-25 : -5)); }
__host__ __device__ constexpr int offOf(int j){ return dxOf(j)*SW + dyOf(j); }

typedef unsigned long long u64;

__device__ __forceinline__ u64 pack2(float a, float b){
    u64 r;
    asm("mov.b64 %0, {%1,%2};" : "=l"(r) : "f"(a), "f"(b));
    return r;
}
__device__ __forceinline__ void fma2(u64 &acc, u64 a, u64 b){
    asm("fma.rn.f32x2 %0, %1, %2, %0;" : "+l"(acc) : "l"(a), "l"(b));
}
__device__ __forceinline__ float2 unpack2(u64 v){
    float2 f;
    asm("mov.b64 {%0,%1}, %2;" : "=f"(f.x), "=f"(f.y) : "l"(v));
    return f;
}

__global__ __launch_bounds__(NTHR, 2)
void pkc2d_kernel(const float* __restrict__ x,
                  const float* __restrict__ cw,
                  const float* __restrict__ cb,
                  float* __restrict__ out)
{
    extern __shared__ float sm[];
    float*    xs  = sm;                      // [c][sy][sx] 16 x 18 x 42
    float*    ws  = sm + XS_FLOATS;          // [r][c][o]   16 x 16 x 32
    float*    cbs = ws + WS_FLOATS;          // [32]
    unsigned* selp = (unsigned*)(cbs + CB_FLOATS); // [r][tid] 16 x 256

    const int tx = threadIdx.x, ty = threadIdx.y;
    const int tid = ty*TW + tx;
    const int gx0 = blockIdx.x*TW, gy0 = blockIdx.y*TH;
    const int bz  = blockIdx.z;

    const float* xb = x + (size_t)bz * CCH * HW;

    // ---- cooperative loads ----
    for (int i = tid; i < XS_FLOATS; i += NTHR) {
        int c   = i / CPLANE;
        int rem = i - c*CPLANE;
        int sy  = rem / SW;
        int sx  = rem - sy*SW;
        int gy  = gy0 + sy - 5;
        int gxp = gx0 + sx - 5;
        float v = 0.f;
        if ((unsigned)gy < (unsigned)HH && (unsigned)gxp < (unsigned)WWIDTH)
            v = xb[c*HW + gy*WWIDTH + gxp];
        xs[i] = v;
    }
    // ws[((r*16)+c)*32 + o] = cw[o*256 + c*16 + r]
    for (int i = tid; i < WS_FLOATS; i += NTHR) {
        int o  = i & 31;
        int rc = i >> 5;
        int r  = rc >> 4;
        int c  = rc & 15;
        ws[i] = cw[o*256 + c*16 + r];
    }
    if (tid < 32) cbs[tid] = cb[tid];
    __syncthreads();

    // ================= Phase 1: per-own-pixel selection =================
    {
        const int base = (ty+5)*SW + (tx+5);

        float xc[CCH];
        #pragma unroll
        for (int c = 0; c < CCH; ++c) xc[c] = xs[c*CPLANE + base];

        // sims (sequential channel-order mul+add to track the reference reduction)
        float sims[NOFF];
        #pragma unroll
        for (int j = 0; j < NOFF; ++j) {
            const int off = offOf(j);
            float s = 0.f;
            #pragma unroll
            for (int c = 0; c < CCH; ++c)
                s = __fadd_rn(s, __fmul_rn(xs[c*CPLANE + base + off], xc[c]));
            s *= 0.0625f;
            sims[j] = 1.0f / (1.0f + expf(-s));
        }

        // Stable argsort rank via one compare per unordered pair:
        //   e_ij = (sims[i] <= sims[j]) for i<j
        //   rank_i = (#{k<i: sims[k]<=sims[i]}) + (#{j>i: sims[j]<sims[i]})
        //          = T_i + (NOFF-1-i) - S_i
        // seed rk[i] = NOFF-1-i, then rk[j] += e, rk[i] -= e.
        int rk[NOFF];
        #pragma unroll
        for (int i = 0; i < NOFF; ++i) rk[i] = NOFF - 1 - i;
        #pragma unroll
        for (int i = 0; i < NOFF; ++i) {
            #pragma unroll
            for (int j = i+1; j < NOFF; ++j) {
                if (sims[i] <= sims[j]) { rk[j] += 1; rk[i] -= 1; }
            }
        }
        #pragma unroll
        for (int j = 0; j < NOFF; ++j) {
            if (rk[j] < NSEL)
                selp[rk[j]*NTHR + tid] = (unsigned)(offOf(j) + 512);
        }
    }
    __syncthreads();

    // ================= Phase 2: pixel-pair / half-OUTC mat-vec =================
    // thread t: ph = t>>7 -> o in [16*ph, 16*ph+16); pixels p0 = t&127 (rows 0..3)
    // and p1 = p0+128 (rows 4..7) of the 32x8 tile.
    const int pp = tid & 127;
    const int ph = tid >> 7;
    const int px = pp & 31;
    const int py = pp >> 5;

    const int b0 = (py+5)*SW + (px+5);
    const int b1 = b0 + 4*SW;

    float xc0[CCH], xc1[CCH];
    #pragma unroll
    for (int c = 0; c < CCH; ++c) {
        xc0[c] = xs[c*CPLANE + b0];
        xc1[c] = xs[c*CPLANE + b1];
    }

    u64 accA[8], accB[8];
    #pragma unroll
    for (int q = 0; q < 8; ++q) {
        u64 seed = pack2(cbs[ph*16 + 2*q], cbs[ph*16 + 2*q + 1]);
        accA[q] = seed;
        accB[q] = seed;
    }

    #pragma unroll 1
    for (int r = 0; r < NSEL; ++r) {
        const int a0 = b0 + (int)selp[r*NTHR + pp]       - 512;
        const int a1 = b1 + (int)selp[r*NTHR + pp + 128] - 512;
        const ulonglong2* wp =
            reinterpret_cast<const ulonglong2*>(ws + (r << 9) + (ph << 4));
        #pragma unroll
        for (int c = 0; c < CCH; ++c) {
            const float d0 = xc0[c] - xs[c*CPLANE + a0];
            const float d1 = xc1[c] - xs[c*CPLANE + a1];
            const u64 d0p = pack2(d0, d0);
            const u64 d1p = pack2(d1, d1);
            ulonglong2 wa = wp[c*8 + 0];
            ulonglong2 wb = wp[c*8 + 1];
            ulonglong2 wc = wp[c*8 + 2];
            ulonglong2 wd = wp[c*8 + 3];
            fma2(accA[0], wa.x, d0p); fma2(accB[0], wa.x, d1p);
            fma2(accA[1], wa.y, d0p); fma2(accB[1], wa.y, d1p);
            fma2(accA[2], wb.x, d0p); fma2(accB[2], wb.x, d1p);
            fma2(accA[3], wb.y, d0p); fma2(accB[3], wb.y, d1p);
            fma2(accA[4], wc.x, d0p); fma2(accB[4], wc.x, d1p);
            fma2(accA[5], wc.y, d0p); fma2(accB[5], wc.y, d1p);
            fma2(accA[6], wd.x, d0p); fma2(accB[6], wd.x, d1p);
            fma2(accA[7], wd.y, d0p); fma2(accB[7], wd.y, d1p);
        }
    }

    // ---- store: 16 o-channels x 2 pixels ----
    const int gx = gx0 + px;
    const int gy_a = gy0 + py;
    const int gy_b = gy_a + 4;
    float* ob = out + (size_t)bz*OUTC*HW + (size_t)(ph*16)*HW + gx;
    #pragma unroll
    for (int q = 0; q < 8; ++q) {
        float2 va = unpack2(accA[q]);
        float2 vb = unpack2(accB[q]);
        ob[(2*q  )*HW + gy_a*WWIDTH] = va.x;
        ob[(2*q+1)*HW + gy_a*WWIDTH] = va.y;
        ob[(2*q  )*HW + gy_b*WWIDTH] = vb.x;
        ob[(2*q+1)*HW + gy_b*WWIDTH] = vb.y;
    }
}

extern "C" void kernel_launch(void* const* d_in, const int* in_sizes, int n_in,
                              void* d_out, int out_size)
{
    const float* x  = (const float*)d_in[0];
    const float* cw = (const float*)d_in[1];
    const float* cb = (const float*)d_in[2];
    float* out = (float*)d_out;

    cudaFuncSetAttribute(pkc2d_kernel,
                         cudaFuncAttributeMaxDynamicSharedMemorySize, SMEM_BYTES);

    dim3 block(TW, TH, 1);
    dim3 grid(WWIDTH/TW, HH/TH, B_);
    pkc2d_kernel<<<grid, block, SMEM_BYTES>>>(x, cw, cb, out);
}

// round 6
// speedup vs baseline: 1.1640x; 1.0594x over previous
#include <cuda_runtime.h>
#include <math.h>

// x (2,16,256,256) f32, conv_w (32,16,4,4), conv_b (32) -> out (2,32,256,256) f32.
// Ring of 40 offsets (radius 5), stable-select 16 smallest sigmoid-sims,
// rank-indexed 32x(16*16) mat-vec per pixel.

#define B_      2
#define CCH     16
#define NC2     (CCH/2)        // 8 float2 channel-pairs
#define HH      256
#define WWIDTH  256
#define HW      (HH*WWIDTH)
#define OUTC    32
#define NOFF    40
#define NSEL    16

#define TW 32
#define TH 8
#define NTHR (TW*TH)           // 256
#define SW 42                  // TW + 2*5
#define SH 18                  // TH + 2*5
#define CPLANE (SW*SH)         // 756
#define XS_FLOATS (CPLANE*CCH)        // 12096 floats (= CPLANE*NC2 float2)
#define WS_FLOATS (NSEL*CCH*OUTC)     // 8192
#define CB_FLOATS 32
#define SEL_WORDS (NSEL*NTHR)         // 4096
#define SMEM_BYTES ((XS_FLOATS + WS_FLOATS + CB_FLOATS + SEL_WORDS)*4)

// Ring offsets, order matching _prf_offsets:
//  j 0..10 : dx=-5,   dy=j-5
//  j 11..19: dx=j-15, dy=+5
//  j 20..30: dx=+5,   dy=j-25
//  j 31..39: dx=j-35, dy=-5
__host__ __device__ constexpr int dxOf(int j){ return j<11 ? -5 : (j<20 ? j-15 : (j<31 ? 5 : j-35)); }
__host__ __device__ constexpr int dyOf(int j){ return j<11 ? j-5 : (j<20 ? 5 : (j<31 ? j-25 : -5)); }
__host__ __device__ constexpr int offOf(int j){ return dxOf(j)*SW + dyOf(j); }

typedef unsigned long long u64;

__device__ __forceinline__ u64 pack2(float a, float b){
    u64 r;
    asm("mov.b64 %0, {%1,%2};" : "=l"(r) : "f"(a), "f"(b));
    return r;
}
__device__ __forceinline__ void fma2(u64 &acc, u64 a, u64 b){
    asm("fma.rn.f32x2 %0, %1, %2, %0;" : "+l"(acc) : "l"(a), "l"(b));
}
__device__ __forceinline__ float2 unpack2(u64 v){
    float2 f;
    asm("mov.b64 {%0,%1}, %2;" : "=f"(f.x), "=f"(f.y) : "l"(v));
    return f;
}

__global__ __launch_bounds__(NTHR, 2)
void pkc2d_kernel(const float* __restrict__ x,
                  const float* __restrict__ cw,
                  const float* __restrict__ cb,
                  float* __restrict__ out)
{
    extern __shared__ float sm[];
    float2*   xs2 = reinterpret_cast<float2*>(sm);   // [c2][sy][sx] 8 x 18 x 42 float2
    float*    ws  = sm + XS_FLOATS;                  // [r][c][o]   16 x 16 x 32
    float*    cbs = ws + WS_FLOATS;                  // [32]
    unsigned* selp = (unsigned*)(cbs + CB_FLOATS);   // [r][tid] 16 x 256

    const int tx = threadIdx.x, ty = threadIdx.y;
    const int tid = ty*TW + tx;
    const int gx0 = blockIdx.x*TW, gy0 = blockIdx.y*TH;
    const int bz  = blockIdx.z;

    const float* xb = x + (size_t)bz * CCH * HW;

    // ---- cooperative loads: halo tile as channel-paired float2 ----
    for (int i = tid; i < CPLANE*NC2; i += NTHR) {
        int c2  = i / CPLANE;
        int rem = i - c2*CPLANE;
        int sy  = rem / SW;
        int sx  = rem - sy*SW;
        int gy  = gy0 + sy - 5;
        int gxp = gx0 + sx - 5;
        float2 v = make_float2(0.f, 0.f);
        if ((unsigned)gy < (unsigned)HH && (unsigned)gxp < (unsigned)WWIDTH) {
            const float* p = xb + (2*c2)*HW + gy*WWIDTH + gxp;
            v.x = p[0];
            v.y = p[HW];
        }
        xs2[i] = v;
    }
    // ws[((r*16)+c)*32 + o] = cw[o*256 + c*16 + r]
    for (int i = tid; i < WS_FLOATS; i += NTHR) {
        int o  = i & 31;
        int rc = i >> 5;
        int r  = rc >> 4;
        int c  = rc & 15;
        ws[i] = cw[o*256 + c*16 + r];
    }
    if (tid < 32) cbs[tid] = cb[tid];
    __syncthreads();

    // ================= Phase 1: per-own-pixel selection =================
    {
        const int base = (ty+5)*SW + (tx+5);

        float2 xc[NC2];
        #pragma unroll
        for (int c2 = 0; c2 < NC2; ++c2) xc[c2] = xs2[c2*CPLANE + base];

        // sims: sequential channel-order mul+add (matches reference reduction),
        // then sigmoid — REQUIRED: its fp32 rounding creates ties that the
        // stable argsort resolves by index; ranking raw dots breaks them
        // differently (verified: rel_err 6.7e-4 -> 1.8e-3 without it).
        float sims[NOFF];
        #pragma unroll
        for (int j = 0; j < NOFF; ++j) {
            const int off = offOf(j);
            float s = 0.f;
            #pragma unroll
            for (int c2 = 0; c2 < NC2; ++c2) {
                const float2 v = xs2[c2*CPLANE + base + off];
                s = __fadd_rn(s, __fmul_rn(v.x, xc[c2].x));
                s = __fadd_rn(s, __fmul_rn(v.y, xc[c2].y));
            }
            s *= 0.0625f;
            sims[j] = 1.0f / (1.0f + expf(-s));
        }

        // Stable argsort rank, one compare per unordered pair:
        //   seed rk[i] = NOFF-1-i; for i<j: e=(sims[i]<=sims[j]); rk[j]+=e; rk[i]-=e;
        int rk[NOFF];
        #pragma unroll
        for (int i = 0; i < NOFF; ++i) rk[i] = NOFF - 1 - i;
        #pragma unroll
        for (int i = 0; i < NOFF; ++i) {
            #pragma unroll
            for (int j = i+1; j < NOFF; ++j) {
                if (sims[i] <= sims[j]) { rk[j] += 1; rk[i] -= 1; }
            }
        }
        #pragma unroll
        for (int j = 0; j < NOFF; ++j) {
            if (rk[j] < NSEL)
                selp[rk[j]*NTHR + tid] = (unsigned)(offOf(j) + 512);
        }
    }
    __syncthreads();

    // ================= Phase 2: pixel-pair / half-OUTC mat-vec =================
    // thread t: ph = t>>7 -> o in [16*ph, 16*ph+16); pixels p0 = t&127 (rows 0..3)
    // and p1 = p0+128 (rows 4..7) of the 32x8 tile.
    const int pp = tid & 127;
    const int ph = tid >> 7;
    const int px = pp & 31;
    const int py = pp >> 5;

    const int b0 = (py+5)*SW + (px+5);
    const int b1 = b0 + 4*SW;

    float2 xc0[NC2], xc1[NC2];
    #pragma unroll
    for (int c2 = 0; c2 < NC2; ++c2) {
        xc0[c2] = xs2[c2*CPLANE + b0];
        xc1[c2] = xs2[c2*CPLANE + b1];
    }

    u64 accA[8], accB[8];
    #pragma unroll
    for (int q = 0; q < 8; ++q) {
        u64 seed = pack2(cbs[ph*16 + 2*q], cbs[ph*16 + 2*q + 1]);
        accA[q] = seed;
        accB[q] = seed;
    }

    #pragma unroll 1
    for (int r = 0; r < NSEL; ++r) {
        const int a0 = b0 + (int)selp[r*NTHR + pp]       - 512;
        const int a1 = b1 + (int)selp[r*NTHR + pp + 128] - 512;
        const ulonglong2* wp =
            reinterpret_cast<const ulonglong2*>(ws + (r << 9) + (ph << 4));
        #pragma unroll
        for (int c2 = 0; c2 < NC2; ++c2) {
            const float2 v0 = xs2[c2*CPLANE + a0];
            const float2 v1 = xs2[c2*CPLANE + a1];
            const u64 dx0 = pack2(xc0[c2].x - v0.x, xc0[c2].x - v0.x);
            const u64 dy0 = pack2(xc0[c2].y - v0.y, xc0[c2].y - v0.y);
            const u64 dx1 = pack2(xc1[c2].x - v1.x, xc1[c2].x - v1.x);
            const u64 dy1 = pack2(xc1[c2].y - v1.y, xc1[c2].y - v1.y);
            // channel c = 2*c2 (weights chunk cA), c = 2*c2+1 (chunk cB)
            const ulonglong2* cA = wp + (2*c2  )*8;
            const ulonglong2* cB = wp + (2*c2+1)*8;
            ulonglong2 wa = cA[0], wb = cA[1], wc = cA[2], wd = cA[3];
            fma2(accA[0], wa.x, dx0); fma2(accB[0], wa.x, dx1);
            fma2(accA[1], wa.y, dx0); fma2(accB[1], wa.y, dx1);
            fma2(accA[2], wb.x, dx0); fma2(accB[2], wb.x, dx1);
            fma2(accA[3], wb.y, dx0); fma2(accB[3], wb.y, dx1);
            fma2(accA[4], wc.x, dx0); fma2(accB[4], wc.x, dx1);
            fma2(accA[5], wc.y, dx0); fma2(accB[5], wc.y, dx1);
            fma2(accA[6], wd.x, dx0); fma2(accB[6], wd.x, dx1);
            fma2(accA[7], wd.y, dx0); fma2(accB[7], wd.y, dx1);
            wa = cB[0]; wb = cB[1]; wc = cB[2]; wd = cB[3];
            fma2(accA[0], wa.x, dy0); fma2(accB[0], wa.x, dy1);
            fma2(accA[1], wa.y, dy0); fma2(accB[1], wa.y, dy1);
            fma2(accA[2], wb.x, dy0); fma2(accB[2], wb.x, dy1);
            fma2(accA[3], wb.y, dy0); fma2(accB[3], wb.y, dy1);
            fma2(accA[4], wc.x, dy0); fma2(accB[4], wc.x, dy1);
            fma2(accA[5], wc.y, dy0); fma2(accB[5], wc.y, dy1);
            fma2(accA[6], wd.x, dy0); fma2(accB[6], wd.x, dy1);
            fma2(accA[7], wd.y, dy0); fma2(accB[7], wd.y, dy1);
        }
    }

    // ---- store: 16 o-channels x 2 pixels ----
    const int gx = gx0 + px;
    const int gy_a = gy0 + py;
    const int gy_b = gy_a + 4;
    float* ob = out + (size_t)bz*OUTC*HW + (size_t)(ph*16)*HW + gx;
    #pragma unroll
    for (int q = 0; q < 8; ++q) {
        float2 va = unpack2(accA[q]);
        float2 vb = unpack2(accB[q]);
        ob[(2*q  )*HW + gy_a*WWIDTH] = va.x;
        ob[(2*q+1)*HW + gy_a*WWIDTH] = va.y;
        ob[(2*q  )*HW + gy_b*WWIDTH] = vb.x;
        ob[(2*q+1)*HW + gy_b*WWIDTH] = vb.y;
    }
}

extern "C" void kernel_launch(void* const* d_in, const int* in_sizes, int n_in,
                              void* d_out, int out_size)
{
    const float* x  = (const float*)d_in[0];
    const float* cw = (const float*)d_in[1];
    const float* cb = (const float*)d_in[2];
    float* out = (float*)d_out;

    cudaFuncSetAttribute(pkc2d_kernel,
                         cudaFuncAttributeMaxDynamicSharedMemorySize, SMEM_BYTES);

    dim3 block(TW, TH, 1);
    dim3 grid(WWIDTH/TW, HH/TH, B_);
    pkc2d_kernel<<<grid, block, SMEM_BYTES>>>(x, cw, cb, out);
}